// round 8
// baseline (speedup 1.0000x reference)
#include <cuda_runtime.h>
#include <cstdint>

// Problem constants (fixed by the dataset)
#define BB      8
#define N_GRID  4096
#define N_OFF   4096

#define OSPLIT  16
#define OCHUNK  (N_OFF / OSPLIT)      // 256 off-grid points per block
#define NPAIR   (OCHUNK / 2)          // 128 point-pairs in shared
#define NGROUP  (NPAIR / 2)           // 64 4-point groups
#define GPT     2                     // grid points per thread
#define GTILE   (256 * GPT)           // 512 grid points per block
#define NXT     (N_GRID / GTILE)      // 8 grid tiles

// Partial sums: [OSPLIT][B*N_GRID] float2 (4 MB scratch) + arrival tickets.
__device__ float2 g_partial[OSPLIT * BB * N_GRID];
__device__ unsigned int g_tickets[BB * NXT];   // zero-init; monotonic (mod-16 test)

// 0.5 * log2(e): folds -0.5 and base-2 conversion into the quadratic coeffs
// so each weight is a bare ex2.approx.
#define HL2E 0.72134752044448170f

// ---- packed f32x2 helpers (sm_100+, .b64 operands) ----
__device__ __forceinline__ uint64_t pk2(float lo, float hi) {
    uint64_t r; asm("mov.b64 %0, {%1,%2};" : "=l"(r) : "f"(lo), "f"(hi)); return r;
}
__device__ __forceinline__ void unpk2(uint64_t v, float& lo, float& hi) {
    asm("mov.b64 {%0,%1}, %2;" : "=f"(lo), "=f"(hi) : "l"(v));
}
__device__ __forceinline__ uint64_t add2(uint64_t a, uint64_t b) {
    uint64_t r; asm("add.rn.f32x2 %0, %1, %2;" : "=l"(r) : "l"(a), "l"(b)); return r;
}
__device__ __forceinline__ uint64_t fma2(uint64_t a, uint64_t b, uint64_t c) {
    uint64_t r; asm("fma.rn.f32x2 %0, %1, %2, %3;" : "=l"(r) : "l"(a), "l"(b), "l"(c)); return r;
}

// Packed-f16 exp2 of a packed f32x2: one MUFU for two weights.
// s is post-cancellation (small where it matters) so the f16 quantization
// costs only |s|*2^-11 in the exponent. Lane order preserved (lo, hi):
// cvt.rn.f16x2.f32 d, a, b  ->  d.hi = cvt(a), d.lo = cvt(b).
__device__ __forceinline__ uint64_t wexp2h(uint64_t s2) {
    uint64_t r;
    asm("{\n\t"
        ".reg .f32 lo, hi, glo, ghi;\n\t"
        ".reg .b32 h2;\n\t"
        ".reg .b16 hlo, hhi;\n\t"
        "mov.b64 {lo, hi}, %1;\n\t"
        "cvt.rn.f16x2.f32 h2, hi, lo;\n\t"
        "ex2.approx.f16x2 h2, h2;\n\t"
        "mov.b32 {hlo, hhi}, h2;\n\t"
        "cvt.f32.f16 glo, hlo;\n\t"
        "cvt.f32.f16 ghi, hhi;\n\t"
        "mov.b64 %0, {glo, ghi};\n\t"
        "}" : "=l"(r) : "l"(s2));
    return r;
}

__global__ void __launch_bounds__(256) conv_fused(
    const float* __restrict__ xo,   // [B, N_OFF, 2]
    const float* __restrict__ yo,   // [B, N_OFF, 2]
    const float* __restrict__ xg,   // [B, N_GRID, 2]
    const float* __restrict__ yg,   // [B, N_GRID, 2]
    const float* __restrict__ lsp,  // [2]
    float* __restrict__ out)
{
    // Pair p=(i,j):  sx[p] = (2K0bx_i, 2K0bx_j, 2K1by_i, 2K1by_j)
    //                sy[p] = (y0_i, y0_j, y1_i, y1_j)
    //                scb[p] = (cb_i, cb_j),  cb = -(K0bx^2 + K1by^2)
    __shared__ float4 sx[NPAIR];
    __shared__ float2 scb[NPAIR];
    __shared__ float4 sy[NPAIR];
    __shared__ float  kk[2];
    __shared__ int    s_do_reduce;

    const int b     = blockIdx.y;
    const int gx    = blockIdx.x;
    const int obase = blockIdx.z * OCHUNK;

    if (threadIdx.x < 2) {
        float p  = lsp[threadIdx.x];
        float ls = 1e-5f + log1pf(expf(p));
        kk[threadIdx.x] = HL2E / (ls * ls);    // K_d
    }
    __syncthreads();
    const float K0 = kk[0];
    const float K1 = kk[1];

    // Cooperative tile build: one float4 of x covers a pair (i, j=i+1).
    const float4* xo4 = (const float4*)(xo + (size_t)b * N_OFF * 2) + obase / 2;
    const float4* yo4 = (const float4*)(yo + (size_t)b * N_OFF * 2) + obase / 2;
    for (int i = threadIdx.x; i < NPAIR; i += 256) {
        float4 xv = xo4[i];   // (bx_i, by_i, bx_j, by_j)
        float4 yv = yo4[i];   // (y0_i, y1_i, y0_j, y1_j)
        sx[i]  = make_float4(2.f * K0 * xv.x, 2.f * K0 * xv.z,
                             2.f * K1 * xv.y, 2.f * K1 * xv.w);
        scb[i] = make_float2(-(K0 * xv.x * xv.x + K1 * xv.y * xv.y),
                             -(K0 * xv.z * xv.z + K1 * xv.w * xv.w));
        sy[i]  = make_float4(yv.x, yv.z, yv.y, yv.w);
    }
    __syncthreads();

    // Two grid points per thread: g0 = base+tid, g1 = g0+256.
    const int g0 = gx * GTILE + threadIdx.x;
    const int g1 = g0 + 256;
    float2 xg0 = ((const float2*)xg)[(size_t)b * N_GRID + g0];
    float2 xg1 = ((const float2*)xg)[(size_t)b * N_GRID + g1];
    const uint64_t a00_0 = pk2(xg0.x, xg0.x);
    const uint64_t a11_0 = pk2(xg0.y, xg0.y);
    const float   cA0   = -(K0 * xg0.x * xg0.x + K1 * xg0.y * xg0.y);
    const uint64_t cA2_0 = pk2(cA0, cA0);
    const uint64_t a00_1 = pk2(xg1.x, xg1.x);
    const uint64_t a11_1 = pk2(xg1.y, xg1.y);
    const float   cA1   = -(K0 * xg1.x * xg1.x + K1 * xg1.y * xg1.y);
    const uint64_t cA2_1 = pk2(cA1, cA1);

    uint64_t p00 = 0ull, p01 = 0ull;   // gp0: packed y0-, y1- partials
    uint64_t p10 = 0ull, p11 = 0ull;   // gp1

    uint32_t axy, acb, ayy;
    asm("{ .reg .u64 t; cvta.to.shared.u64 t, %1; cvt.u32.u64 %0, t; }"
        : "=r"(axy) : "l"((const void*)sx));
    asm("{ .reg .u64 t; cvta.to.shared.u64 t, %1; cvt.u32.u64 %0, t; }"
        : "=r"(acb) : "l"((const void*)scb));
    asm("{ .reg .u64 t; cvta.to.shared.u64 t, %1; cvt.u32.u64 %0, t; }"
        : "=r"(ayy) : "l"((const void*)sy));

#pragma unroll 4
    for (int q = 0; q < NGROUP; q++) {
        uint64_t bxA, byA, bxB, byB, cbA, cbB, y0A, y1A, y0B, y1B;
        asm("ld.shared.v2.b64 {%0,%1}, [%2];"
            : "=l"(bxA), "=l"(byA) : "r"(axy + q * 32));
        asm("ld.shared.v2.b64 {%0,%1}, [%2];"
            : "=l"(bxB), "=l"(byB) : "r"(axy + q * 32 + 16));
        asm("ld.shared.v2.b64 {%0,%1}, [%2];"
            : "=l"(cbA), "=l"(cbB) : "r"(acb + q * 16));
        asm("ld.shared.v2.b64 {%0,%1}, [%2];"
            : "=l"(y0A), "=l"(y1A) : "r"(ayy + q * 32));
        asm("ld.shared.v2.b64 {%0,%1}, [%2];"
            : "=l"(y0B), "=l"(y1B) : "r"(ayy + q * 32 + 16));

        // ---- grid point 0 ----
        uint64_t sA0 = fma2(bxA, a00_0, cbA);
        sA0 = fma2(byA, a11_0, sA0);
        sA0 = add2(sA0, cA2_0);
        uint64_t sB0 = fma2(bxB, a00_0, cbB);
        sB0 = fma2(byB, a11_0, sB0);
        sB0 = add2(sB0, cA2_0);
        uint64_t wA0 = wexp2h(sA0);
        uint64_t wB0 = wexp2h(sB0);
        p00 = fma2(wA0, y0A, p00);
        p01 = fma2(wA0, y1A, p01);
        p00 = fma2(wB0, y0B, p00);
        p01 = fma2(wB0, y1B, p01);

        // ---- grid point 1 ----
        uint64_t sA1 = fma2(bxA, a00_1, cbA);
        sA1 = fma2(byA, a11_1, sA1);
        sA1 = add2(sA1, cA2_1);
        uint64_t sB1 = fma2(bxB, a00_1, cbB);
        sB1 = fma2(byB, a11_1, sB1);
        sB1 = add2(sB1, cA2_1);
        uint64_t wA1 = wexp2h(sA1);
        uint64_t wB1 = wexp2h(sB1);
        p10 = fma2(wA1, y0A, p10);
        p11 = fma2(wA1, y1A, p11);
        p10 = fma2(wB1, y0B, p10);
        p11 = fma2(wB1, y1B, p11);
    }

    {
        float e, o, e1, o1;
        unpk2(p00, e, o);  unpk2(p01, e1, o1);
        g_partial[(size_t)(blockIdx.z * BB + b) * N_GRID + g0] =
            make_float2(e + o, e1 + o1);
        unpk2(p10, e, o);  unpk2(p11, e1, o1);
        g_partial[(size_t)(blockIdx.z * BB + b) * N_GRID + g1] =
            make_float2(e + o, e1 + o1);
    }

    // ---- fused reduction: last-arriving block per (b, gx) reduces ----
    __threadfence();
    if (threadIdx.x == 0) {
        unsigned old = atomicAdd(&g_tickets[b * NXT + gx], 1u);
        s_do_reduce = ((old % OSPLIT) == OSPLIT - 1);
    }
    __syncthreads();
    if (!s_do_reduce) return;
    __threadfence();   // acquire side: see all partials

    float4* outy = (float4*)(out + (size_t)BB * N_GRID * 2);
#pragma unroll
    for (int k = 0; k < GPT; k++) {
        int g = (k == 0) ? g0 : g1;
        float2 xv = (k == 0) ? xg0 : xg1;
        ((float2*)out)[(size_t)b * N_GRID + g] = xv;

        float2 yon = ((const float2*)yg)[(size_t)b * N_GRID + g];
        float sxr = 0.f, syr = 0.f;
#pragma unroll
        for (int p = 0; p < OSPLIT; p++) {   // fixed order -> deterministic
            float2 v = g_partial[(size_t)(p * BB + b) * N_GRID + g];
            sxr += v.x;
            syr += v.y;
        }
        outy[(size_t)b * N_GRID + g] = make_float4(yon.x, yon.y, sxr, syr);
    }
}

extern "C" void kernel_launch(void* const* d_in, const int* in_sizes, int n_in,
                              void* d_out, int out_size) {
    const float* xo  = (const float*)d_in[0];  // xc_off_grid
    const float* yo  = (const float*)d_in[1];  // yc_off_grid
    const float* xg  = (const float*)d_in[2];  // xc_on_grid
    const float* yg  = (const float*)d_in[3];  // yc_on_grid
    const float* lsp = (const float*)d_in[4];  // lengthscale_param

    conv_fused<<<dim3(NXT, BB, OSPLIT), 256>>>(xo, yo, xg, yg, lsp, (float*)d_out);
}

// round 9
// speedup vs baseline: 1.0999x; 1.0999x over previous
#include <cuda_runtime.h>
#include <cstdint>

// Problem constants (fixed by the dataset)
#define BB      8
#define N_GRID  4096
#define N_OFF   4096

#define OSPLIT  16
#define OCHUNK  (N_OFF / OSPLIT)      // 256 off-grid points per block
#define NPAIR   (OCHUNK / 2)          // 128 point-pairs in shared
#define NGROUP  (NPAIR / 2)           // 64 4-point groups
#define GPT     2                     // grid points per thread
#define GTILE   (256 * GPT)           // 512 grid points per block
#define NXT     (N_GRID / GTILE)      // 8 grid tiles

// Partial sums: [OSPLIT][B*N_GRID] float2 (4 MB scratch) + arrival tickets.
__device__ float2 g_partial[OSPLIT * BB * N_GRID];
__device__ unsigned int g_tickets[BB * NXT];   // zero-init; monotonic (mod-16 test)

// 0.5 * log2(e): folds -0.5 and base-2 conversion into the quadratic coeffs
// so each weight is a bare ex2.approx.
#define HL2E 0.72134752044448170f

// ---- packed f32x2 helpers (sm_100+, .b64 operands) ----
__device__ __forceinline__ uint64_t pk2(float lo, float hi) {
    uint64_t r; asm("mov.b64 %0, {%1,%2};" : "=l"(r) : "f"(lo), "f"(hi)); return r;
}
__device__ __forceinline__ void unpk2(uint64_t v, float& lo, float& hi) {
    asm("mov.b64 {%0,%1}, %2;" : "=f"(lo), "=f"(hi) : "l"(v));
}
__device__ __forceinline__ uint64_t add2(uint64_t a, uint64_t b) {
    uint64_t r; asm("add.rn.f32x2 %0, %1, %2;" : "=l"(r) : "l"(a), "l"(b)); return r;
}
__device__ __forceinline__ uint64_t fma2(uint64_t a, uint64_t b, uint64_t c) {
    uint64_t r; asm("fma.rn.f32x2 %0, %1, %2, %3;" : "=l"(r) : "l"(a), "l"(b), "l"(c)); return r;
}
__device__ __forceinline__ float ex2(float x) {
    float r; asm("ex2.approx.ftz.f32 %0, %1;" : "=f"(r) : "f"(x)); return r;
}

__global__ void __launch_bounds__(256, 6) conv_fused(
    const float* __restrict__ xo,   // [B, N_OFF, 2]
    const float* __restrict__ yo,   // [B, N_OFF, 2]
    const float* __restrict__ xg,   // [B, N_GRID, 2]
    const float* __restrict__ yg,   // [B, N_GRID, 2]
    const float* __restrict__ lsp,  // [2]
    float* __restrict__ out)
{
    // Pair p=(i,j):  sx[p] = (2K0bx_i, 2K0bx_j, 2K1by_i, 2K1by_j)
    //                sy[p] = (y0_i, y0_j, y1_i, y1_j)
    //                scb[p] = (cb_i, cb_j),  cb = -(K0bx^2 + K1by^2)
    __shared__ float4 sx[NPAIR];
    __shared__ float2 scb[NPAIR];
    __shared__ float4 sy[NPAIR];
    __shared__ float  kk[2];
    __shared__ int    s_do_reduce;

    const int b     = blockIdx.y;
    const int gx    = blockIdx.x;
    const int obase = blockIdx.z * OCHUNK;

    if (threadIdx.x < 2) {
        float p  = lsp[threadIdx.x];
        float ls = 1e-5f + log1pf(expf(p));
        kk[threadIdx.x] = HL2E / (ls * ls);    // K_d
    }
    __syncthreads();
    const float K0 = kk[0];
    const float K1 = kk[1];

    // Cooperative tile build: one float4 of x covers a pair (i, j=i+1).
    const float4* xo4 = (const float4*)(xo + (size_t)b * N_OFF * 2) + obase / 2;
    const float4* yo4 = (const float4*)(yo + (size_t)b * N_OFF * 2) + obase / 2;
    for (int i = threadIdx.x; i < NPAIR; i += 256) {
        float4 xv = xo4[i];   // (bx_i, by_i, bx_j, by_j)
        float4 yv = yo4[i];   // (y0_i, y1_i, y0_j, y1_j)
        sx[i]  = make_float4(2.f * K0 * xv.x, 2.f * K0 * xv.z,
                             2.f * K1 * xv.y, 2.f * K1 * xv.w);
        scb[i] = make_float2(-(K0 * xv.x * xv.x + K1 * xv.y * xv.y),
                             -(K0 * xv.z * xv.z + K1 * xv.w * xv.w));
        sy[i]  = make_float4(yv.x, yv.z, yv.y, yv.w);
    }
    __syncthreads();

    // Two grid points per thread: g0 = base+tid, g1 = g0+256.
    const int g0 = gx * GTILE + threadIdx.x;
    const int g1 = g0 + 256;
    float2 xg0 = ((const float2*)xg)[(size_t)b * N_GRID + g0];
    float2 xg1 = ((const float2*)xg)[(size_t)b * N_GRID + g1];
    const uint64_t a00_0 = pk2(xg0.x, xg0.x);
    const uint64_t a11_0 = pk2(xg0.y, xg0.y);
    const float   cA0   = -(K0 * xg0.x * xg0.x + K1 * xg0.y * xg0.y);
    const uint64_t cA2_0 = pk2(cA0, cA0);
    const uint64_t a00_1 = pk2(xg1.x, xg1.x);
    const uint64_t a11_1 = pk2(xg1.y, xg1.y);
    const float   cA1   = -(K0 * xg1.x * xg1.x + K1 * xg1.y * xg1.y);
    const uint64_t cA2_1 = pk2(cA1, cA1);

    uint64_t p00 = 0ull, p01 = 0ull;   // gp0: packed y0-, y1- partials
    uint64_t p10 = 0ull, p11 = 0ull;   // gp1

    uint32_t axy, acb, ayy;
    asm("{ .reg .u64 t; cvta.to.shared.u64 t, %1; cvt.u32.u64 %0, t; }"
        : "=r"(axy) : "l"((const void*)sx));
    asm("{ .reg .u64 t; cvta.to.shared.u64 t, %1; cvt.u32.u64 %0, t; }"
        : "=r"(acb) : "l"((const void*)scb));
    asm("{ .reg .u64 t; cvta.to.shared.u64 t, %1; cvt.u32.u64 %0, t; }"
        : "=r"(ayy) : "l"((const void*)sy));

#pragma unroll 4
    for (int q = 0; q < NGROUP; q++) {
        uint64_t bxA, byA, bxB, byB, cbA, cbB, y0A, y1A, y0B, y1B;
        asm("ld.shared.v2.b64 {%0,%1}, [%2];"
            : "=l"(bxA), "=l"(byA) : "r"(axy + q * 32));
        asm("ld.shared.v2.b64 {%0,%1}, [%2];"
            : "=l"(bxB), "=l"(byB) : "r"(axy + q * 32 + 16));
        asm("ld.shared.v2.b64 {%0,%1}, [%2];"
            : "=l"(cbA), "=l"(cbB) : "r"(acb + q * 16));
        asm("ld.shared.v2.b64 {%0,%1}, [%2];"
            : "=l"(y0A), "=l"(y1A) : "r"(ayy + q * 32));
        asm("ld.shared.v2.b64 {%0,%1}, [%2];"
            : "=l"(y0B), "=l"(y1B) : "r"(ayy + q * 32 + 16));

        // ---- grid point 0 ----
        uint64_t sA0 = fma2(bxA, a00_0, cbA);
        sA0 = fma2(byA, a11_0, sA0);
        sA0 = add2(sA0, cA2_0);
        uint64_t sB0 = fma2(bxB, a00_0, cbB);
        sB0 = fma2(byB, a11_0, sB0);
        sB0 = add2(sB0, cA2_0);
        float si, sj, sk, sl;
        unpk2(sA0, si, sj);
        unpk2(sB0, sk, sl);
        uint64_t wA0 = pk2(ex2(si), ex2(sj));
        uint64_t wB0 = pk2(ex2(sk), ex2(sl));
        p00 = fma2(wA0, y0A, p00);
        p01 = fma2(wA0, y1A, p01);
        p00 = fma2(wB0, y0B, p00);
        p01 = fma2(wB0, y1B, p01);

        // ---- grid point 1 ----
        uint64_t sA1 = fma2(bxA, a00_1, cbA);
        sA1 = fma2(byA, a11_1, sA1);
        sA1 = add2(sA1, cA2_1);
        uint64_t sB1 = fma2(bxB, a00_1, cbB);
        sB1 = fma2(byB, a11_1, sB1);
        sB1 = add2(sB1, cA2_1);
        unpk2(sA1, si, sj);
        unpk2(sB1, sk, sl);
        uint64_t wA1 = pk2(ex2(si), ex2(sj));
        uint64_t wB1 = pk2(ex2(sk), ex2(sl));
        p10 = fma2(wA1, y0A, p10);
        p11 = fma2(wA1, y1A, p11);
        p10 = fma2(wB1, y0B, p10);
        p11 = fma2(wB1, y1B, p11);
    }

    {
        float e, o, e1, o1;
        unpk2(p00, e, o);  unpk2(p01, e1, o1);
        g_partial[(size_t)(blockIdx.z * BB + b) * N_GRID + g0] =
            make_float2(e + o, e1 + o1);
        unpk2(p10, e, o);  unpk2(p11, e1, o1);
        g_partial[(size_t)(blockIdx.z * BB + b) * N_GRID + g1] =
            make_float2(e + o, e1 + o1);
    }

    // ---- fused reduction: last-arriving block per (b, gx) reduces ----
    __threadfence();
    if (threadIdx.x == 0) {
        unsigned old = atomicAdd(&g_tickets[b * NXT + gx], 1u);
        s_do_reduce = ((old % OSPLIT) == OSPLIT - 1);
    }
    __syncthreads();
    if (!s_do_reduce) return;
    __threadfence();   // acquire side: see all partials

    float4* outy = (float4*)(out + (size_t)BB * N_GRID * 2);
#pragma unroll
    for (int k = 0; k < GPT; k++) {
        int g = (k == 0) ? g0 : g1;
        float2 xv = (k == 0) ? xg0 : xg1;
        ((float2*)out)[(size_t)b * N_GRID + g] = xv;

        float2 yon = ((const float2*)yg)[(size_t)b * N_GRID + g];
        float sxr = 0.f, syr = 0.f;
#pragma unroll
        for (int p = 0; p < OSPLIT; p++) {   // fixed order -> deterministic
            float2 v = g_partial[(size_t)(p * BB + b) * N_GRID + g];
            sxr += v.x;
            syr += v.y;
        }
        outy[(size_t)b * N_GRID + g] = make_float4(yon.x, yon.y, sxr, syr);
    }
}

extern "C" void kernel_launch(void* const* d_in, const int* in_sizes, int n_in,
                              void* d_out, int out_size) {
    const float* xo  = (const float*)d_in[0];  // xc_off_grid
    const float* yo  = (const float*)d_in[1];  // yc_off_grid
    const float* xg  = (const float*)d_in[2];  // xc_on_grid
    const float* yg  = (const float*)d_in[3];  // yc_on_grid
    const float* lsp = (const float*)d_in[4];  // lengthscale_param

    conv_fused<<<dim3(NXT, BB, OSPLIT), 256>>>(xo, yo, xg, yg, lsp, (float*)d_out);
}